// round 3
// baseline (speedup 1.0000x reference)
#include <cuda_runtime.h>
#include <math.h>

// Problem constants
#define BSZ   8
#define NPTS  4096
#define CDIM  128
#define KTOP  9
#define MROWS (BSZ * NPTS)   // 32768
#define EPSBN 1e-5f

// ---------------- scratch (device globals; no allocation allowed) ----------------
__device__ float g_h  [MROWS * CDIM];   // fc1 output -> normalized h
__device__ float g_agg[MROWS * CDIM];   // max-relative aggregation
__device__ float g_t2 [MROWS * CDIM];   // graph-conv linear out -> hg
__device__ float g_sq [MROWS];          // row squared norms of h
__device__ float g_psum[128 * 128];     // per-block partial column sums
__device__ float g_psq [128 * 128];     // per-block partial column sumsq
__device__ float g_mean[128];
__device__ float g_rstd[128];

// =================================================================================
// Tiled SGEMM:  out[M x 128] = A[M x 128] @ W[128 x 128] (+ bias) (+= if acc)
// Block: 128 rows x 128 cols, 256 threads, 8x8 microtile, K chunked by 32.
// =================================================================================
__global__ __launch_bounds__(256) void gemm128(const float* __restrict__ A,
                                               const float* __restrict__ W,
                                               const float* __restrict__ bias,
                                               float* __restrict__ out,
                                               int accFlag)
{
    __shared__ float As[32 * 132];   // [k][m], padded
    __shared__ float Ws[32 * 132];   // [k][n], padded
    const int t  = threadIdx.x;
    const int tx = t & 15, ty = t >> 4;
    const int r0 = blockIdx.x * 128;

    float c[8][8];
#pragma unroll
    for (int i = 0; i < 8; i++)
#pragma unroll
        for (int j = 0; j < 8; j++) c[i][j] = 0.f;

    for (int kc = 0; kc < 128; kc += 32) {
        __syncthreads();
#pragma unroll
        for (int i = 0; i < 4; i++) {
            int lin = t + i * 256;              // [0,1024) float4 slots, 8 per row
            int m = lin >> 3, kq = lin & 7;
            float4 v = *(const float4*)&A[(size_t)(r0 + m) * 128 + kc + kq * 4];
            As[(kq * 4 + 0) * 132 + m] = v.x;
            As[(kq * 4 + 1) * 132 + m] = v.y;
            As[(kq * 4 + 2) * 132 + m] = v.z;
            As[(kq * 4 + 3) * 132 + m] = v.w;
        }
#pragma unroll
        for (int i = 0; i < 4; i++) {
            int lin = t + i * 256;              // [0,1024), 32 float4 per k-row
            int k = lin >> 5, n4 = lin & 31;
            float4 v = *(const float4*)&W[(size_t)(kc + k) * 128 + n4 * 4];
            *(float4*)&Ws[k * 132 + n4 * 4] = v;
        }
        __syncthreads();
#pragma unroll 8
        for (int k = 0; k < 32; k++) {
            float4 a0 = *(const float4*)&As[k * 132 + ty * 8];
            float4 a1 = *(const float4*)&As[k * 132 + ty * 8 + 4];
            float4 b0 = *(const float4*)&Ws[k * 132 + tx * 8];
            float4 b1 = *(const float4*)&Ws[k * 132 + tx * 8 + 4];
            float a[8] = {a0.x, a0.y, a0.z, a0.w, a1.x, a1.y, a1.z, a1.w};
            float b[8] = {b0.x, b0.y, b0.z, b0.w, b1.x, b1.y, b1.z, b1.w};
#pragma unroll
            for (int i = 0; i < 8; i++)
#pragma unroll
                for (int j = 0; j < 8; j++) c[i][j] = fmaf(a[i], b[j], c[i][j]);
        }
    }

    float bv[8];
#pragma unroll
    for (int j = 0; j < 8; j++) bv[j] = bias ? bias[tx * 8 + j] : 0.f;

#pragma unroll
    for (int i = 0; i < 8; i++) {
        size_t base = (size_t)(r0 + ty * 8 + i) * 128 + tx * 8;
        float4 v0 = make_float4(c[i][0] + bv[0], c[i][1] + bv[1],
                                c[i][2] + bv[2], c[i][3] + bv[3]);
        float4 v1 = make_float4(c[i][4] + bv[4], c[i][5] + bv[5],
                                c[i][6] + bv[6], c[i][7] + bv[7]);
        if (accFlag) {
            float4 e0 = *(const float4*)&out[base];
            float4 e1 = *(const float4*)&out[base + 4];
            v0.x += e0.x; v0.y += e0.y; v0.z += e0.z; v0.w += e0.w;
            v1.x += e1.x; v1.y += e1.y; v1.z += e1.z; v1.w += e1.w;
        }
        *(float4*)&out[base]     = v0;
        *(float4*)&out[base + 4] = v1;
    }
}

// =================================================================================
// Deterministic per-channel batch stats (two stages, fixed reduction order).
// =================================================================================
__global__ void colstat_partial(const float* __restrict__ X)
{
    const int t = threadIdx.x;        // channel
    const int b = blockIdx.x;         // row chunk
    const int base = b * 256;
    float s = 0.f, s2 = 0.f;
    for (int r = 0; r < 256; r++) {
        float v = X[(size_t)(base + r) * 128 + t];
        s += v; s2 += v * v;
    }
    g_psum[b * 128 + t] = s;
    g_psq [b * 128 + t] = s2;
}

__global__ void colstat_final()
{
    const int t = threadIdx.x;
    float s = 0.f, s2 = 0.f;
    for (int b = 0; b < 128; b++) { s += g_psum[b * 128 + t]; s2 += g_psq[b * 128 + t]; }
    float m   = s / (float)MROWS;
    float var = s2 / (float)MROWS - m * m;
    g_mean[t] = m;
    g_rstd[t] = rsqrtf(var + EPSBN);
}

// =================================================================================
// BN apply. mode: 0 = plain, 1 = + exact GELU, 2 = + residual.
// =================================================================================
__global__ void bn_apply(const float* __restrict__ X, const float* __restrict__ gamma,
                         const float* __restrict__ beta, const float* __restrict__ resid,
                         float* __restrict__ Y, int mode)
{
    const int i4 = blockIdx.x * blockDim.x + threadIdx.x;
    const size_t i = (size_t)i4 * 4;
    const int ch = (int)(i & 127);
    float4 v  = *(const float4*)&X[i];
    float4 ga = *(const float4*)&gamma[ch];
    float4 be = *(const float4*)&beta[ch];
    float4 mn = *(const float4*)&g_mean[ch];
    float4 rs = *(const float4*)&g_rstd[ch];
    float o[4];
    o[0] = ga.x * (v.x - mn.x) * rs.x + be.x;
    o[1] = ga.y * (v.y - mn.y) * rs.y + be.y;
    o[2] = ga.z * (v.z - mn.z) * rs.z + be.z;
    o[3] = ga.w * (v.w - mn.w) * rs.w + be.w;
    if (mode == 1) {
#pragma unroll
        for (int j = 0; j < 4; j++)
            o[j] = 0.5f * o[j] * (1.f + erff(o[j] * 0.70710678118654752f));
    } else if (mode == 2) {
        float4 r = *(const float4*)&resid[i];
        o[0] += r.x; o[1] += r.y; o[2] += r.z; o[3] += r.w;
    }
    *(float4*)&Y[i] = make_float4(o[0], o[1], o[2], o[3]);
}

// Row squared norms (warp per row).
__global__ void rowsq(const float* __restrict__ X, float* __restrict__ sq)
{
    const int warp = threadIdx.x >> 5, lane = threadIdx.x & 31;
    const int row = blockIdx.x * 8 + warp;
    float4 v = *(const float4*)&X[(size_t)row * 128 + lane * 4];
    float s = v.x * v.x + v.y * v.y + v.z * v.z + v.w * v.w;
#pragma unroll
    for (int o = 16; o; o >>= 1) s += __shfl_xor_sync(0xffffffffu, s, o);
    if (lane == 0) sq[row] = s;
}

// =================================================================================
// KNN + max-relative aggregation, fused.
// Block = one 128-row query tile of one batch. Iterates 32 column tiles of 128:
// 128x128x128 fp32 GEMM microtile -> distance keys (sq[j]-2*dot) to shared ->
// 128 selector threads keep a stable sorted top-9 (strict <, ascending j scan ==
// lax.top_k tie-breaking). Ends with cooperative gather + max-relative agg.
// =================================================================================
#define KNN_SMEM (128 * 132 * 4 * 2 + 128 * 129 * 4 + 128 * 4)

__global__ __launch_bounds__(256, 1) void knn_agg(const float* __restrict__ h,
                                                  const float* __restrict__ sq,
                                                  float* __restrict__ agg)
{
    extern __shared__ float sm[];
    float* Qs   = sm;                    // [k][m] 128x132
    float* Cs   = sm + 128 * 132;        // [k][n] 128x132
    float* Dist = Cs + 128 * 132;        // [row][col] 128x129
    float* sqn  = Dist + 128 * 129;      // [128]

    const int t  = threadIdx.x;
    const int tx = t & 15, ty = t >> 4;
    const int b    = blockIdx.y;
    const int bOff = b * NPTS;
    const int r0   = blockIdx.x * 128;

    // Load query tile (k-major, stays resident)
#pragma unroll
    for (int i = 0; i < 16; i++) {
        int lin = t + i * 256;            // [0,4096): 32 float4 per row
        int m = lin >> 5, kq = lin & 31;
        float4 v = *(const float4*)&h[(size_t)(bOff + r0 + m) * 128 + kq * 4];
        Qs[(kq * 4 + 0) * 132 + m] = v.x;
        Qs[(kq * 4 + 1) * 132 + m] = v.y;
        Qs[(kq * 4 + 2) * 132 + m] = v.z;
        Qs[(kq * 4 + 3) * 132 + m] = v.w;
    }

    float best[KTOP];
    int   bidx[KTOP];
#pragma unroll
    for (int p = 0; p < KTOP; p++) { best[p] = 3.0e38f; bidx[p] = 0; }
    float thr = 3.0e38f;

    for (int ct = 0; ct < 32; ct++) {
        __syncthreads();   // prior selection done before Cs/Dist overwrite
#pragma unroll
        for (int i = 0; i < 16; i++) {
            int lin = t + i * 256;
            int m = lin >> 5, kq = lin & 31;
            float4 v = *(const float4*)&h[(size_t)(bOff + ct * 128 + m) * 128 + kq * 4];
            Cs[(kq * 4 + 0) * 132 + m] = v.x;
            Cs[(kq * 4 + 1) * 132 + m] = v.y;
            Cs[(kq * 4 + 2) * 132 + m] = v.z;
            Cs[(kq * 4 + 3) * 132 + m] = v.w;
        }
        if (t < 128) sqn[t] = sq[bOff + ct * 128 + t];
        __syncthreads();

        float c[8][8];
#pragma unroll
        for (int i = 0; i < 8; i++)
#pragma unroll
            for (int j = 0; j < 8; j++) c[i][j] = 0.f;

#pragma unroll 8
        for (int k = 0; k < 128; k++) {
            float4 a0 = *(const float4*)&Qs[k * 132 + ty * 8];
            float4 a1 = *(const float4*)&Qs[k * 132 + ty * 8 + 4];
            float4 b0 = *(const float4*)&Cs[k * 132 + tx * 8];
            float4 b1 = *(const float4*)&Cs[k * 132 + tx * 8 + 4];
            float a[8] = {a0.x, a0.y, a0.z, a0.w, a1.x, a1.y, a1.z, a1.w};
            float bb[8] = {b0.x, b0.y, b0.z, b0.w, b1.x, b1.y, b1.z, b1.w};
#pragma unroll
            for (int i = 0; i < 8; i++)
#pragma unroll
                for (int j = 0; j < 8; j++) c[i][j] = fmaf(a[i], bb[j], c[i][j]);
        }

        // distance keys: sq[j] - 2*dot  (row-constant sq[i] dropped; order-preserving)
#pragma unroll
        for (int i = 0; i < 8; i++)
#pragma unroll
            for (int j = 0; j < 8; j++)
                Dist[(ty * 8 + i) * 129 + tx * 8 + j] = sqn[tx * 8 + j] - 2.f * c[i][j];
        __syncthreads();

        if (t < 128) {
            const int jg0 = ct * 128;
            for (int j = 0; j < 128; j++) {
                float d = Dist[t * 129 + j];
                if (d < thr) {
                    int p = KTOP - 1;
                    while (p > 0 && d < best[p - 1]) {
                        best[p] = best[p - 1];
                        bidx[p] = bidx[p - 1];
                        p--;
                    }
                    best[p] = d;
                    bidx[p] = jg0 + j;
                    thr = best[KTOP - 1];
                }
            }
        }
    }

    __syncthreads();
    int* nb = (int*)Dist;   // reuse
    if (t < 128) {
#pragma unroll
        for (int p = 0; p < KTOP; p++) nb[t * KTOP + p] = bidx[p];
    }
    __syncthreads();

    // Cooperative gather + max-relative aggregation: warp per 16 rows.
    const int warp = t >> 5, lane = t & 31;
    for (int rr = 0; rr < 16; rr++) {
        int row = warp * 16 + rr;
        float q0 = Qs[(lane * 4 + 0) * 132 + row];
        float q1 = Qs[(lane * 4 + 1) * 132 + row];
        float q2 = Qs[(lane * 4 + 2) * 132 + row];
        float q3 = Qs[(lane * 4 + 3) * 132 + row];
        float m0 = -3.0e38f, m1 = -3.0e38f, m2 = -3.0e38f, m3 = -3.0e38f;
#pragma unroll
        for (int p = 0; p < KTOP; p++) {
            int j = nb[row * KTOP + p];
            float4 v = *(const float4*)&h[(size_t)(bOff + j) * 128 + lane * 4];
            m0 = fmaxf(m0, v.x); m1 = fmaxf(m1, v.y);
            m2 = fmaxf(m2, v.z); m3 = fmaxf(m3, v.w);
        }
        *(float4*)&agg[(size_t)(bOff + r0 + row) * 128 + lane * 4] =
            make_float4(m0 - q0, m1 - q1, m2 - q2, m3 - q3);
    }
}

// =================================================================================
// Launch: fc1 -> BN -> rownorms -> KNN+agg -> gconv(2C->C) -> BN+GELU -> fc2 -> BN+res
// =================================================================================
extern "C" void kernel_launch(void* const* d_in, const int* in_sizes, int n_in,
                              void* d_out, int out_size)
{
    const float* x   = (const float*)d_in[0];
    const float* W1  = (const float*)d_in[1];
    const float* b1  = (const float*)d_in[2];
    const float* g1  = (const float*)d_in[3];
    const float* be1 = (const float*)d_in[4];
    const float* Wg  = (const float*)d_in[5];
    const float* bg  = (const float*)d_in[6];
    const float* gg  = (const float*)d_in[7];
    const float* beg = (const float*)d_in[8];
    const float* W2  = (const float*)d_in[9];
    const float* b2  = (const float*)d_in[10];
    const float* g2  = (const float*)d_in[11];
    const float* be2 = (const float*)d_in[12];
    float* out = (float*)d_out;

    float *ph, *pagg, *pt2, *psq;
    cudaGetSymbolAddress((void**)&ph,   g_h);
    cudaGetSymbolAddress((void**)&pagg, g_agg);
    cudaGetSymbolAddress((void**)&pt2,  g_t2);
    cudaGetSymbolAddress((void**)&psq,  g_sq);

    cudaFuncSetAttribute(knn_agg, cudaFuncAttributeMaxDynamicSharedMemorySize, KNN_SMEM);

    // fc1 + BN
    gemm128<<<256, 256>>>(x, W1, b1, ph, 0);
    colstat_partial<<<128, 128>>>(ph);
    colstat_final<<<1, 128>>>();
    bn_apply<<<4096, 256>>>(ph, g1, be1, nullptr, ph, 0);

    // KNN + max-relative aggregation
    rowsq<<<4096, 256>>>(ph, psq);
    knn_agg<<<dim3(32, 8), 256, KNN_SMEM>>>(ph, psq, pagg);

    // graph conv MLP: cat([h, agg]) @ Wg + bg, BN, GELU
    gemm128<<<256, 256>>>(ph, Wg, nullptr, pt2, 0);
    gemm128<<<256, 256>>>(pagg, Wg + 128 * 128, bg, pt2, 1);
    colstat_partial<<<128, 128>>>(pt2);
    colstat_final<<<1, 128>>>();
    bn_apply<<<4096, 256>>>(pt2, gg, beg, nullptr, pt2, 1);

    // fc2 + BN + residual
    gemm128<<<256, 256>>>(pt2, W2, b2, out, 0);
    colstat_partial<<<128, 128>>>(out);
    colstat_final<<<1, 128>>>();
    bn_apply<<<4096, 256>>>(out, g2, be2, x, out, 2);
}

// round 6
// speedup vs baseline: 2.3608x; 2.3608x over previous
#include <cuda_runtime.h>
#include <cuda_bf16.h>
#include <math.h>
#include <stdint.h>

// Problem constants
#define BSZ   8
#define NPTS  4096
#define CDIM  128
#define KTOP  9
#define MROWS (BSZ * NPTS)   // 32768
#define EPSBN 1e-5f

// ---------------- scratch (device globals; no allocation allowed) ----------------
__device__ float g_h  [MROWS * CDIM];
__device__ float g_agg[MROWS * CDIM];
__device__ float g_t2 [MROWS * CDIM];
__device__ float g_sq [MROWS];
__device__ __nv_bfloat16 g_hh[MROWS * CDIM];   // bf16 hi split of h
__device__ __nv_bfloat16 g_hm[MROWS * CDIM];   // bf16 mid split
__device__ __nv_bfloat16 g_hl[MROWS * CDIM];   // bf16 lo split
__device__ float g_psum[128 * 128];
__device__ float g_psq [128 * 128];
__device__ float g_mean[128];
__device__ float g_rstd[128];

// =================================================================================
// PTX helpers (baseline sm_80+ ISA only: ldmatrix / mma.sync / cp.async)
// =================================================================================
__device__ __forceinline__ uint32_t smem_u32(const void* p) {
    uint32_t a;
    asm("{ .reg .u64 t; cvta.to.shared.u64 t, %1; cvt.u32.u64 %0, t; }" : "=r"(a) : "l"(p));
    return a;
}
__device__ __forceinline__ void ldsm4(uint32_t* r, uint32_t a) {
    asm volatile("ldmatrix.sync.aligned.m8n8.x4.shared.b16 {%0,%1,%2,%3}, [%4];"
                 : "=r"(r[0]), "=r"(r[1]), "=r"(r[2]), "=r"(r[3]) : "r"(a));
}
__device__ __forceinline__ void ldsm2(uint32_t* r, uint32_t a) {
    asm volatile("ldmatrix.sync.aligned.m8n8.x2.shared.b16 {%0,%1}, [%2];"
                 : "=r"(r[0]), "=r"(r[1]) : "r"(a));
}
__device__ __forceinline__ void mma16816(float* c, const uint32_t* a, uint32_t b0, uint32_t b1) {
    asm volatile("mma.sync.aligned.m16n8k16.row.col.f32.bf16.bf16.f32 "
                 "{%0,%1,%2,%3},{%4,%5,%6,%7},{%8,%9},{%0,%1,%2,%3};"
                 : "+f"(c[0]), "+f"(c[1]), "+f"(c[2]), "+f"(c[3])
                 : "r"(a[0]), "r"(a[1]), "r"(a[2]), "r"(a[3]), "r"(b0), "r"(b1));
}
__device__ __forceinline__ void cp16(uint32_t dst, const void* src) {
    asm volatile("cp.async.cg.shared.global [%0], [%1], 16;" :: "r"(dst), "l"(src));
}
#define CP_COMMIT() asm volatile("cp.async.commit_group;" ::: "memory")
#define CP_WAIT(n)  asm volatile("cp.async.wait_group %0;" :: "n"(n) : "memory")

// =================================================================================
// Tiled SGEMM (128-dim fc layers): out[M x 128] = A[M x 128] @ W (+bias) (+= if acc)
// =================================================================================
__global__ __launch_bounds__(256) void gemm128(const float* __restrict__ A,
                                               const float* __restrict__ W,
                                               const float* __restrict__ bias,
                                               float* __restrict__ out,
                                               int accFlag)
{
    __shared__ float As[32 * 132];
    __shared__ float Ws[32 * 132];
    const int t  = threadIdx.x;
    const int tx = t & 15, ty = t >> 4;
    const int r0 = blockIdx.x * 128;

    float c[8][8];
#pragma unroll
    for (int i = 0; i < 8; i++)
#pragma unroll
        for (int j = 0; j < 8; j++) c[i][j] = 0.f;

    for (int kc = 0; kc < 128; kc += 32) {
        __syncthreads();
#pragma unroll
        for (int i = 0; i < 4; i++) {
            int lin = t + i * 256;
            int m = lin >> 3, kq = lin & 7;
            float4 v = *(const float4*)&A[(size_t)(r0 + m) * 128 + kc + kq * 4];
            As[(kq * 4 + 0) * 132 + m] = v.x;
            As[(kq * 4 + 1) * 132 + m] = v.y;
            As[(kq * 4 + 2) * 132 + m] = v.z;
            As[(kq * 4 + 3) * 132 + m] = v.w;
        }
#pragma unroll
        for (int i = 0; i < 4; i++) {
            int lin = t + i * 256;
            int k = lin >> 5, n4 = lin & 31;
            float4 v = *(const float4*)&W[(size_t)(kc + k) * 128 + n4 * 4];
            *(float4*)&Ws[k * 132 + n4 * 4] = v;
        }
        __syncthreads();
#pragma unroll 8
        for (int k = 0; k < 32; k++) {
            float4 a0 = *(const float4*)&As[k * 132 + ty * 8];
            float4 a1 = *(const float4*)&As[k * 132 + ty * 8 + 4];
            float4 b0 = *(const float4*)&Ws[k * 132 + tx * 8];
            float4 b1 = *(const float4*)&Ws[k * 132 + tx * 8 + 4];
            float a[8] = {a0.x, a0.y, a0.z, a0.w, a1.x, a1.y, a1.z, a1.w};
            float b[8] = {b0.x, b0.y, b0.z, b0.w, b1.x, b1.y, b1.z, b1.w};
#pragma unroll
            for (int i = 0; i < 8; i++)
#pragma unroll
                for (int j = 0; j < 8; j++) c[i][j] = fmaf(a[i], b[j], c[i][j]);
        }
    }

    float bv[8];
#pragma unroll
    for (int j = 0; j < 8; j++) bv[j] = bias ? bias[tx * 8 + j] : 0.f;

#pragma unroll
    for (int i = 0; i < 8; i++) {
        size_t base = (size_t)(r0 + ty * 8 + i) * 128 + tx * 8;
        float4 v0 = make_float4(c[i][0] + bv[0], c[i][1] + bv[1], c[i][2] + bv[2], c[i][3] + bv[3]);
        float4 v1 = make_float4(c[i][4] + bv[4], c[i][5] + bv[5], c[i][6] + bv[6], c[i][7] + bv[7]);
        if (accFlag) {
            float4 e0 = *(const float4*)&out[base];
            float4 e1 = *(const float4*)&out[base + 4];
            v0.x += e0.x; v0.y += e0.y; v0.z += e0.z; v0.w += e0.w;
            v1.x += e1.x; v1.y += e1.y; v1.z += e1.z; v1.w += e1.w;
        }
        *(float4*)&out[base]     = v0;
        *(float4*)&out[base + 4] = v1;
    }
}

// ============================ BN stats (deterministic) ============================
__global__ void colstat_partial(const float* __restrict__ X)
{
    const int t = threadIdx.x;
    const int b = blockIdx.x;
    const int base = b * 256;
    float s = 0.f, s2 = 0.f;
    for (int r = 0; r < 256; r++) {
        float v = X[(size_t)(base + r) * 128 + t];
        s += v; s2 += v * v;
    }
    g_psum[b * 128 + t] = s;
    g_psq [b * 128 + t] = s2;
}

__global__ void colstat_final()
{
    const int t = threadIdx.x;
    float s = 0.f, s2 = 0.f;
    for (int b = 0; b < 128; b++) { s += g_psum[b * 128 + t]; s2 += g_psq[b * 128 + t]; }
    float m   = s / (float)MROWS;
    float var = s2 / (float)MROWS - m * m;
    g_mean[t] = m;
    g_rstd[t] = rsqrtf(var + EPSBN);
}

// ============ BN apply (mode 1: +GELU, mode 2: +residual) ============
__global__ void bn_apply(const float* __restrict__ X, const float* __restrict__ gamma,
                         const float* __restrict__ beta, const float* __restrict__ resid,
                         float* __restrict__ Y, int mode)
{
    const int i4 = blockIdx.x * blockDim.x + threadIdx.x;
    const size_t i = (size_t)i4 * 4;
    const int ch = (int)(i & 127);
    float4 v  = *(const float4*)&X[i];
    float4 ga = *(const float4*)&gamma[ch];
    float4 be = *(const float4*)&beta[ch];
    float4 mn = *(const float4*)&g_mean[ch];
    float4 rs = *(const float4*)&g_rstd[ch];
    float o[4];
    o[0] = ga.x * (v.x - mn.x) * rs.x + be.x;
    o[1] = ga.y * (v.y - mn.y) * rs.y + be.y;
    o[2] = ga.z * (v.z - mn.z) * rs.z + be.z;
    o[3] = ga.w * (v.w - mn.w) * rs.w + be.w;
    if (mode == 1) {
#pragma unroll
        for (int j = 0; j < 4; j++)
            o[j] = 0.5f * o[j] * (1.f + erff(o[j] * 0.70710678118654752f));
    } else if (mode == 2) {
        float4 r = *(const float4*)&resid[i];
        o[0] += r.x; o[1] += r.y; o[2] += r.z; o[3] += r.w;
    }
    *(float4*)&Y[i] = make_float4(o[0], o[1], o[2], o[3]);
}

// ===== BN apply + 3-way bf16 split + row sq-norm (fc1 output), warp per row =====
__global__ void bn_split(const float* __restrict__ X, const float* __restrict__ gamma,
                         const float* __restrict__ beta, float* __restrict__ H,
                         __nv_bfloat16* __restrict__ Hh, __nv_bfloat16* __restrict__ Hm,
                         __nv_bfloat16* __restrict__ Hl, float* __restrict__ sqo)
{
    const int wid = threadIdx.x >> 5, lane = threadIdx.x & 31;
    const int row = blockIdx.x * 8 + wid;
    const int ch = lane * 4;
    const size_t base = (size_t)row * 128 + ch;
    float4 v  = *(const float4*)&X[base];
    float4 ga = *(const float4*)&gamma[ch];
    float4 be = *(const float4*)&beta[ch];
    float4 mn = *(const float4*)&g_mean[ch];
    float4 rs = *(const float4*)&g_rstd[ch];
    float o[4];
    o[0] = ga.x * (v.x - mn.x) * rs.x + be.x;
    o[1] = ga.y * (v.y - mn.y) * rs.y + be.y;
    o[2] = ga.z * (v.z - mn.z) * rs.z + be.z;
    o[3] = ga.w * (v.w - mn.w) * rs.w + be.w;
    *(float4*)&H[base] = make_float4(o[0], o[1], o[2], o[3]);

    __nv_bfloat16 hh[4], hm[4], hl[4];
#pragma unroll
    for (int j = 0; j < 4; j++) {
        hh[j] = __float2bfloat16(o[j]);
        float r = o[j] - __bfloat162float(hh[j]);
        hm[j] = __float2bfloat16(r);
        r -= __bfloat162float(hm[j]);
        hl[j] = __float2bfloat16(r);
    }
    ((__nv_bfloat162*)(Hh + base))[0] = __halves2bfloat162(hh[0], hh[1]);
    ((__nv_bfloat162*)(Hh + base))[1] = __halves2bfloat162(hh[2], hh[3]);
    ((__nv_bfloat162*)(Hm + base))[0] = __halves2bfloat162(hm[0], hm[1]);
    ((__nv_bfloat162*)(Hm + base))[1] = __halves2bfloat162(hm[2], hm[3]);
    ((__nv_bfloat162*)(Hl + base))[0] = __halves2bfloat162(hl[0], hl[1]);
    ((__nv_bfloat162*)(Hl + base))[1] = __halves2bfloat162(hl[2], hl[3]);

    float s = o[0]*o[0] + o[1]*o[1] + o[2]*o[2] + o[3]*o[3];
#pragma unroll
    for (int off = 16; off; off >>= 1) s += __shfl_xor_sync(0xffffffffu, s, off);
    if (lane == 0) sqo[row] = s;
}

// =================================================================================
// KNN + max-relative aggregation via mma.sync bf16 3-split (6 products, ~fp32 acc).
// Block: 256 threads (8 warps), 128 query rows, 64 candidate cols/tile, 64 tiles.
// Q fragments live in registers for the whole kernel. C tiles: cp.async 4-ring.
// Selection fully in registers (per-lane top-9 x 2 rows), merged at the end.
// =================================================================================
#define ROWB   272            // padded bf16 row: 136 halves (conflict-free ldmatrix)
#define SPLITB (64 * ROWB)    // 17408
#define BUFB   (3 * SPLITB)   // 52224 per ring slot
#define SQNS_OFF (4 * BUFB)   // 208896
#define KNN_SMEM (SQNS_OFF + 4 * 256)   // 209920

__device__ __forceinline__ void loadtile(uint32_t smdst,
                                         const __nv_bfloat16* __restrict__ Hh,
                                         const __nv_bfloat16* __restrict__ Hm,
                                         const __nv_bfloat16* __restrict__ Hl,
                                         int rowBase, int t)
{
#pragma unroll
    for (int i = 0; i < 12; i++) {
        int lin = t + i * 256;            // [0,3072)
        int s = lin >> 10, rem = lin & 1023;
        int row = rem >> 4, ch = rem & 15;
        const __nv_bfloat16* sp = (s == 0) ? Hh : (s == 1) ? Hm : Hl;
        cp16(smdst + (uint32_t)(s * SPLITB + row * ROWB + ch * 16),
             (const char*)(sp + (size_t)(rowBase + row) * 128) + ch * 16);
    }
}

// register insertion into sorted top-9 (strict <, stable for ascending-j feed)
#define INS9(Bst, Idx, KEY, J) do {                                        \
    float _k = (KEY); int _j = (J);                                        \
    if (_k < Bst[8]) {                                                     \
        float ck = _k; int cj = _j;                                        \
        _Pragma("unroll")                                                  \
        for (int _p = 0; _p < 9; _p++) {                                   \
            if (ck < Bst[_p]) {                                            \
                float tk = Bst[_p]; int tj = Idx[_p];                      \
                Bst[_p] = ck; Idx[_p] = cj; ck = tk; cj = tj;              \
            }                                                              \
        }                                                                  \
    }                                                                      \
} while (0)

__global__ __launch_bounds__(256, 1) void knn_mma(const __nv_bfloat16* __restrict__ Hh,
                                                  const __nv_bfloat16* __restrict__ Hm,
                                                  const __nv_bfloat16* __restrict__ Hl,
                                                  const float* __restrict__ h,
                                                  const float* __restrict__ sq,
                                                  float* __restrict__ agg)
{
    extern __shared__ __align__(16) char smp[];
    const uint32_t smb = smem_u32(smp);
    const int t = threadIdx.x, w = t >> 5, lane = t & 31;
    const int b = blockIdx.y, bOff = b * NPTS, r0 = blockIdx.x * 128;

    // ---- stage Q tile (128 rows) through ring slots 0,1; extract A fragments ----
    loadtile(smb + 0 * BUFB, Hh, Hm, Hl, bOff + r0, t);
    loadtile(smb + 1 * BUFB, Hh, Hm, Hl, bOff + r0 + 64, t);
    CP_COMMIT();
    CP_WAIT(0);
    __syncthreads();

    uint32_t A[3][8][4];    // [split][kstep][frag]
    {
        const uint32_t abase = smb + (uint32_t)((w >> 2) * BUFB);
        const int rb = (w * 16) & 63;
        const uint32_t aoff = (uint32_t)((rb + (lane & 15)) * ROWB + ((lane >> 4) * 16));
#pragma unroll
        for (int s = 0; s < 3; s++)
#pragma unroll
            for (int ks = 0; ks < 8; ks++)
                ldsm4(A[s][ks], abase + (uint32_t)(s * SPLITB + ks * 32) + aoff);
    }
    __syncthreads();

    // ---- prime the 4-slot ring with tiles 0,1,2 ----
#pragma unroll
    for (int pt = 0; pt < 3; pt++) {
        loadtile(smb + (uint32_t)(pt * BUFB), Hh, Hm, Hl, bOff + pt * 64, t);
        if (t < 16) cp16(smb + (uint32_t)(SQNS_OFF + pt * 256 + t * 16),
                         (const char*)(sq + bOff + pt * 64) + t * 16);
        CP_COMMIT();
    }

    // per-lane top-9 for two accumulator rows
    float bA[9], bB[9];
    int   iA[9], iB[9];
#pragma unroll
    for (int p = 0; p < 9; p++) { bA[p] = 3.0e38f; bB[p] = 3.0e38f; iA[p] = 0; iB[p] = 0; }

    const uint32_t boff = (uint32_t)((lane & 7) * ROWB + ((lane & 8) ? 16 : 0));
    const int cq = 2 * (lane & 3);

    for (int ct = 0; ct < 64; ct++) {
        if (ct < 62)      CP_WAIT(2);
        else if (ct == 62) CP_WAIT(1);
        else               CP_WAIT(0);
        __syncthreads();

        // prefetch tile ct+3 into slot (ct+3)&3 (free: consumed at iter ct-1)
        if (ct + 3 < 64) {
            loadtile(smb + (uint32_t)(((ct + 3) & 3) * BUFB), Hh, Hm, Hl,
                     bOff + (ct + 3) * 64, t);
            if (t < 16) cp16(smb + (uint32_t)(SQNS_OFF + ((ct + 3) & 3) * 256 + t * 16),
                             (const char*)(sq + bOff + (ct + 3) * 64) + t * 16);
            CP_COMMIT();
        }

        const int bi = ct & 3;
        const uint32_t cb = smb + (uint32_t)(bi * BUFB);

        float acc[8][4];
#pragma unroll
        for (int nb = 0; nb < 8; nb++)
#pragma unroll
            for (int q = 0; q < 4; q++) acc[nb][q] = 0.f;

#pragma unroll
        for (int ks = 0; ks < 8; ks++) {
#pragma unroll
            for (int g = 0; g < 2; g++) {
                uint32_t Bf[4][3][2];
#pragma unroll
                for (int n4 = 0; n4 < 4; n4++)
#pragma unroll
                    for (int s = 0; s < 3; s++)
                        ldsm2(Bf[n4][s], cb + (uint32_t)(s * SPLITB + (g * 4 + n4) * 8 * ROWB
                                                         + ks * 32) + boff);
                // products: hh, hm, mh, hl, lh, mm (interleaved over 4 nb for dep distance)
                const int sa[6] = {0, 0, 1, 0, 2, 1};
                const int sb[6] = {0, 1, 0, 2, 0, 1};
#pragma unroll
                for (int p = 0; p < 6; p++)
#pragma unroll
                    for (int n4 = 0; n4 < 4; n4++)
                        mma16816(acc[g * 4 + n4], A[sa[p]][ks],
                                 Bf[n4][sb[p]][0], Bf[n4][sb[p]][1]);
            }
        }

        // in-register selection: key = sq[j] - 2*dot, ascending j within lane
        const float* sqt = (const float*)(smp + SQNS_OFF + bi * 256);
        const int jg0 = ct * 64;
#pragma unroll
        for (int nb = 0; nb < 8; nb++) {
            float s0 = sqt[nb * 8 + cq];
            float s1 = sqt[nb * 8 + cq + 1];
            int c0 = jg0 + nb * 8 + cq;
            INS9(bA, iA, fmaf(-2.f, acc[nb][0], s0), c0);
            INS9(bA, iA, fmaf(-2.f, acc[nb][1], s1), c0 + 1);
            INS9(bB, iB, fmaf(-2.f, acc[nb][2], s0), c0);
            INS9(bB, iB, fmaf(-2.f, acc[nb][3], s1), c0 + 1);
        }
    }

    // ---- merge per-lane candidates: 4 lanes x 9 -> top-9 per row ----
    float* ckey = (float*)smp;                       // [128][36]
    int*   cidx = (int*)(smp + 128 * 36 * 4);        // [128][36]
    int*   nbx  = (int*)(smp + 2 * 128 * 36 * 4);    // [128][9]
    {
        const int rA = w * 16 + (lane >> 2);
        const int rB = rA + 8;
        const int sl = (lane & 3) * 9;
#pragma unroll
        for (int p = 0; p < 9; p++) {
            ckey[rA * 36 + sl + p] = bA[p];  cidx[rA * 36 + sl + p] = iA[p];
            ckey[rB * 36 + sl + p] = bB[p];  cidx[rB * 36 + sl + p] = iB[p];
        }
    }
    __syncthreads();

    if (t < 128) {
        float bk[9]; int bj[9];
#pragma unroll
        for (int p = 0; p < 9; p++) { bk[p] = 3.0e38f; bj[p] = 0x7fffffff; }
        for (int q = 0; q < 36; q++) {
            float k = ckey[t * 36 + q];
            int   j = cidx[t * 36 + q];
            if (k < bk[8] || (k == bk[8] && j < bj[8])) {
                float ck = k; int cj = j;
#pragma unroll
                for (int p = 0; p < 9; p++) {
                    if (ck < bk[p] || (ck == bk[p] && cj < bj[p])) {
                        float tk = bk[p]; int tj = bj[p];
                        bk[p] = ck; bj[p] = cj; ck = tk; cj = tj;
                    }
                }
            }
        }
#pragma unroll
        for (int p = 0; p < 9; p++) nbx[t * 9 + p] = bj[p];
    }
    __syncthreads();

    // ---- cooperative gather + max-relative aggregation (warp per 16 rows) ----
    for (int rr = 0; rr < 16; rr++) {
        const int row = w * 16 + rr;
        float4 q = *(const float4*)&h[(size_t)(bOff + r0 + row) * 128 + lane * 4];
        float m0 = -3.0e38f, m1 = -3.0e38f, m2 = -3.0e38f, m3 = -3.0e38f;
#pragma unroll
        for (int p = 0; p < KTOP; p++) {
            int j = nbx[row * 9 + p];
            float4 v = *(const float4*)&h[(size_t)(bOff + j) * 128 + lane * 4];
            m0 = fmaxf(m0, v.x); m1 = fmaxf(m1, v.y);
            m2 = fmaxf(m2, v.z); m3 = fmaxf(m3, v.w);
        }
        *(float4*)&agg[(size_t)(bOff + r0 + row) * 128 + lane * 4] =
            make_float4(m0 - q.x, m1 - q.y, m2 - q.z, m3 - q.w);
    }
}

// =================================================================================
// Launch sequence
// =================================================================================
extern "C" void kernel_launch(void* const* d_in, const int* in_sizes, int n_in,
                              void* d_out, int out_size)
{
    const float* x   = (const float*)d_in[0];
    const float* W1  = (const float*)d_in[1];
    const float* b1  = (const float*)d_in[2];
    const float* g1  = (const float*)d_in[3];
    const float* be1 = (const float*)d_in[4];
    const float* Wg  = (const float*)d_in[5];
    const float* bg  = (const float*)d_in[6];
    const float* gg  = (const float*)d_in[7];
    const float* beg = (const float*)d_in[8];
    const float* W2  = (const float*)d_in[9];
    const float* b2  = (const float*)d_in[10];
    const float* g2  = (const float*)d_in[11];
    const float* be2 = (const float*)d_in[12];
    float* out = (float*)d_out;

    float *ph, *pagg, *pt2, *psq;
    __nv_bfloat16 *phh, *phm, *phl;
    cudaGetSymbolAddress((void**)&ph,   g_h);
    cudaGetSymbolAddress((void**)&pagg, g_agg);
    cudaGetSymbolAddress((void**)&pt2,  g_t2);
    cudaGetSymbolAddress((void**)&psq,  g_sq);
    cudaGetSymbolAddress((void**)&phh,  g_hh);
    cudaGetSymbolAddress((void**)&phm,  g_hm);
    cudaGetSymbolAddress((void**)&phl,  g_hl);

    cudaFuncSetAttribute(knn_mma, cudaFuncAttributeMaxDynamicSharedMemorySize, KNN_SMEM);

    // fc1 + BN (+ bf16 splits + row norms)
    gemm128<<<256, 256>>>(x, W1, b1, ph, 0);
    colstat_partial<<<128, 128>>>(ph);
    colstat_final<<<1, 128>>>();
    bn_split<<<4096, 256>>>(ph, g1, be1, ph, phh, phm, phl, psq);

    // KNN + max-relative aggregation (tensor cores via mma.sync)
    knn_mma<<<dim3(32, 8), 256, KNN_SMEM>>>(phh, phm, phl, ph, psq, pagg);

    // graph conv MLP: cat([h, agg]) @ Wg + bg, BN, GELU
    gemm128<<<256, 256>>>(ph, Wg, nullptr, pt2, 0);
    gemm128<<<256, 256>>>(pagg, Wg + 128 * 128, bg, pt2, 1);
    colstat_partial<<<128, 128>>>(pt2);
    colstat_final<<<1, 128>>>();
    bn_apply<<<4096, 256>>>(pt2, gg, beg, nullptr, pt2, 1);

    // fc2 + BN + residual
    gemm128<<<256, 256>>>(pt2, W2, b2, out, 0);
    colstat_partial<<<128, 128>>>(out);
    colstat_final<<<1, 128>>>();
    bn_apply<<<4096, 256>>>(out, g2, be2, x, out, 2);
}

// round 7
// speedup vs baseline: 2.3822x; 1.0090x over previous
#include <cuda_runtime.h>
#include <cuda_bf16.h>
#include <math.h>
#include <stdint.h>

// Problem constants
#define BSZ   8
#define NPTS  4096
#define CDIM  128
#define KTOP  9
#define MROWS (BSZ * NPTS)   // 32768
#define EPSBN 1e-5f

// ---------------- scratch (device globals; no allocation allowed) ----------------
__device__ float g_h  [MROWS * CDIM];
__device__ float g_agg[MROWS * CDIM];
__device__ float g_t2 [MROWS * CDIM];
__device__ float g_sq [MROWS];
__device__ __nv_bfloat16 g_hh[MROWS * CDIM];   // bf16 hi split of h
__device__ __nv_bfloat16 g_hm[MROWS * CDIM];   // bf16 mid split
__device__ __nv_bfloat16 g_hl[MROWS * CDIM];   // bf16 lo split
__device__ float g_psum[256 * 128];
__device__ float g_psq [256 * 128];
__device__ float g_mean[128];
__device__ float g_rstd[128];

// =================================================================================
// PTX helpers (baseline sm_80+ ISA only: ldmatrix / mma.sync / cp.async)
// =================================================================================
__device__ __forceinline__ uint32_t smem_u32(const void* p) {
    uint32_t a;
    asm("{ .reg .u64 t; cvta.to.shared.u64 t, %1; cvt.u32.u64 %0, t; }" : "=r"(a) : "l"(p));
    return a;
}
__device__ __forceinline__ void ldsm4(uint32_t* r, uint32_t a) {
    asm volatile("ldmatrix.sync.aligned.m8n8.x4.shared.b16 {%0,%1,%2,%3}, [%4];"
                 : "=r"(r[0]), "=r"(r[1]), "=r"(r[2]), "=r"(r[3]) : "r"(a));
}
__device__ __forceinline__ void mma16816(float* c, const uint32_t* a, uint32_t b0, uint32_t b1) {
    asm volatile("mma.sync.aligned.m16n8k16.row.col.f32.bf16.bf16.f32 "
                 "{%0,%1,%2,%3},{%4,%5,%6,%7},{%8,%9},{%0,%1,%2,%3};"
                 : "+f"(c[0]), "+f"(c[1]), "+f"(c[2]), "+f"(c[3])
                 : "r"(a[0]), "r"(a[1]), "r"(a[2]), "r"(a[3]), "r"(b0), "r"(b1));
}
__device__ __forceinline__ void cp16(uint32_t dst, const void* src) {
    asm volatile("cp.async.cg.shared.global [%0], [%1], 16;" :: "r"(dst), "l"(src));
}
#define CP_COMMIT() asm volatile("cp.async.commit_group;" ::: "memory")
#define CP_WAIT(n)  asm volatile("cp.async.wait_group %0;" :: "n"(n) : "memory")

// =================================================================================
// Tiled SGEMM: out[M x 128] = A[M x 128] @ W (+ A2 @ W[128:]) + bias.
// Fused deterministic column stats (sum / sumsq) into the epilogue.
// =================================================================================
__global__ __launch_bounds__(256) void gemm128(const float* __restrict__ A,
                                               const float* __restrict__ A2,
                                               const float* __restrict__ W,
                                               const float* __restrict__ bias,
                                               float* __restrict__ out)
{
    __shared__ float As[32 * 132];
    __shared__ float Ws[32 * 132];
    const int t  = threadIdx.x;
    const int tx = t & 15, ty = t >> 4;
    const int r0 = blockIdx.x * 128;

    float c[8][8];
#pragma unroll
    for (int i = 0; i < 8; i++)
#pragma unroll
        for (int j = 0; j < 8; j++) c[i][j] = 0.f;

    const int nSrc = A2 ? 2 : 1;
    for (int si = 0; si < nSrc; si++) {
        const float* Ap = si ? A2 : A;
        const float* Wp = W + si * 128 * 128;
        for (int kc = 0; kc < 128; kc += 32) {
            __syncthreads();
#pragma unroll
            for (int i = 0; i < 4; i++) {
                int lin = t + i * 256;
                int m = lin >> 3, kq = lin & 7;
                float4 v = *(const float4*)&Ap[(size_t)(r0 + m) * 128 + kc + kq * 4];
                As[(kq * 4 + 0) * 132 + m] = v.x;
                As[(kq * 4 + 1) * 132 + m] = v.y;
                As[(kq * 4 + 2) * 132 + m] = v.z;
                As[(kq * 4 + 3) * 132 + m] = v.w;
            }
#pragma unroll
            for (int i = 0; i < 4; i++) {
                int lin = t + i * 256;
                int k = lin >> 5, n4 = lin & 31;
                float4 v = *(const float4*)&Wp[(size_t)(kc + k) * 128 + n4 * 4];
                *(float4*)&Ws[k * 132 + n4 * 4] = v;
            }
            __syncthreads();
#pragma unroll 8
            for (int k = 0; k < 32; k++) {
                float4 a0 = *(const float4*)&As[k * 132 + ty * 8];
                float4 a1 = *(const float4*)&As[k * 132 + ty * 8 + 4];
                float4 b0 = *(const float4*)&Ws[k * 132 + tx * 8];
                float4 b1 = *(const float4*)&Ws[k * 132 + tx * 8 + 4];
                float a[8] = {a0.x, a0.y, a0.z, a0.w, a1.x, a1.y, a1.z, a1.w};
                float b[8] = {b0.x, b0.y, b0.z, b0.w, b1.x, b1.y, b1.z, b1.w};
#pragma unroll
                for (int i = 0; i < 8; i++)
#pragma unroll
                    for (int j = 0; j < 8; j++) c[i][j] = fmaf(a[i], b[j], c[i][j]);
            }
        }
    }

    float bv[8];
#pragma unroll
    for (int j = 0; j < 8; j++) bv[j] = bias ? bias[tx * 8 + j] : 0.f;

    float s1[8], s2[8];
#pragma unroll
    for (int j = 0; j < 8; j++) { s1[j] = 0.f; s2[j] = 0.f; }

#pragma unroll
    for (int i = 0; i < 8; i++) {
        size_t base = (size_t)(r0 + ty * 8 + i) * 128 + tx * 8;
        float v[8];
#pragma unroll
        for (int j = 0; j < 8; j++) {
            v[j] = c[i][j] + bv[j];
            s1[j] += v[j];
            s2[j] += v[j] * v[j];
        }
        *(float4*)&out[base]     = make_float4(v[0], v[1], v[2], v[3]);
        *(float4*)&out[base + 4] = make_float4(v[4], v[5], v[6], v[7]);
    }

    // fused column stats: per-thread 8-row sums -> smem -> 128-thread reduce
    __syncthreads();
#pragma unroll
    for (int j = 0; j < 8; j++) {
        As[ty * 128 + tx * 8 + j] = s1[j];
        Ws[ty * 128 + tx * 8 + j] = s2[j];
    }
    __syncthreads();
    if (t < 128) {
        float S = 0.f, Q = 0.f;
#pragma unroll
        for (int g = 0; g < 16; g++) { S += As[g * 128 + t]; Q += Ws[g * 128 + t]; }
        g_psum[blockIdx.x * 128 + t] = S;
        g_psq [blockIdx.x * 128 + t] = Q;
    }
}

__global__ void colstat_final()
{
    const int t = threadIdx.x;
    float s = 0.f, s2 = 0.f;
    for (int b = 0; b < 256; b++) { s += g_psum[b * 128 + t]; s2 += g_psq[b * 128 + t]; }
    float m   = s / (float)MROWS;
    float var = s2 / (float)MROWS - m * m;
    g_mean[t] = m;
    g_rstd[t] = rsqrtf(var + EPSBN);
}

// ============ BN apply (mode 1: +GELU, mode 2: +residual) ============
__global__ void bn_apply(const float* __restrict__ X, const float* __restrict__ gamma,
                         const float* __restrict__ beta, const float* __restrict__ resid,
                         float* __restrict__ Y, int mode)
{
    const int i4 = blockIdx.x * blockDim.x + threadIdx.x;
    const size_t i = (size_t)i4 * 4;
    const int ch = (int)(i & 127);
    float4 v  = *(const float4*)&X[i];
    float4 ga = *(const float4*)&gamma[ch];
    float4 be = *(const float4*)&beta[ch];
    float4 mn = *(const float4*)&g_mean[ch];
    float4 rs = *(const float4*)&g_rstd[ch];
    float o[4];
    o[0] = ga.x * (v.x - mn.x) * rs.x + be.x;
    o[1] = ga.y * (v.y - mn.y) * rs.y + be.y;
    o[2] = ga.z * (v.z - mn.z) * rs.z + be.z;
    o[3] = ga.w * (v.w - mn.w) * rs.w + be.w;
    if (mode == 1) {
#pragma unroll
        for (int j = 0; j < 4; j++)
            o[j] = 0.5f * o[j] * (1.f + erff(o[j] * 0.70710678118654752f));
    } else if (mode == 2) {
        float4 r = *(const float4*)&resid[i];
        o[0] += r.x; o[1] += r.y; o[2] += r.z; o[3] += r.w;
    }
    *(float4*)&Y[i] = make_float4(o[0], o[1], o[2], o[3]);
}

// ===== BN apply + 3-way bf16 split + row sq-norm (fc1 output), warp per row =====
__global__ void bn_split(const float* __restrict__ X, const float* __restrict__ gamma,
                         const float* __restrict__ beta, float* __restrict__ H,
                         __nv_bfloat16* __restrict__ Hh, __nv_bfloat16* __restrict__ Hm,
                         __nv_bfloat16* __restrict__ Hl, float* __restrict__ sqo)
{
    const int wid = threadIdx.x >> 5, lane = threadIdx.x & 31;
    const int row = blockIdx.x * 8 + wid;
    const int ch = lane * 4;
    const size_t base = (size_t)row * 128 + ch;
    float4 v  = *(const float4*)&X[base];
    float4 ga = *(const float4*)&gamma[ch];
    float4 be = *(const float4*)&beta[ch];
    float4 mn = *(const float4*)&g_mean[ch];
    float4 rs = *(const float4*)&g_rstd[ch];
    float o[4];
    o[0] = ga.x * (v.x - mn.x) * rs.x + be.x;
    o[1] = ga.y * (v.y - mn.y) * rs.y + be.y;
    o[2] = ga.z * (v.z - mn.z) * rs.z + be.z;
    o[3] = ga.w * (v.w - mn.w) * rs.w + be.w;
    *(float4*)&H[base] = make_float4(o[0], o[1], o[2], o[3]);

    __nv_bfloat16 hh[4], hm[4], hl[4];
#pragma unroll
    for (int j = 0; j < 4; j++) {
        hh[j] = __float2bfloat16(o[j]);
        float r = o[j] - __bfloat162float(hh[j]);
        hm[j] = __float2bfloat16(r);
        r -= __bfloat162float(hm[j]);
        hl[j] = __float2bfloat16(r);
    }
    ((__nv_bfloat162*)(Hh + base))[0] = __halves2bfloat162(hh[0], hh[1]);
    ((__nv_bfloat162*)(Hh + base))[1] = __halves2bfloat162(hh[2], hh[3]);
    ((__nv_bfloat162*)(Hm + base))[0] = __halves2bfloat162(hm[0], hm[1]);
    ((__nv_bfloat162*)(Hm + base))[1] = __halves2bfloat162(hm[2], hm[3]);
    ((__nv_bfloat162*)(Hl + base))[0] = __halves2bfloat162(hl[0], hl[1]);
    ((__nv_bfloat162*)(Hl + base))[1] = __halves2bfloat162(hl[2], hl[3]);

    float s = o[0]*o[0] + o[1]*o[1] + o[2]*o[2] + o[3]*o[3];
#pragma unroll
    for (int off = 16; off; off >>= 1) s += __shfl_xor_sync(0xffffffffu, s, off);
    if (lane == 0) sqo[row] = s;
}

// =================================================================================
// KNN + max-relative aggregation via mma.sync bf16 3-split (6 products).
// Q tile (128 rows x 3 splits) resident in SMEM; A frags reloaded per k-step
// (12 regs). B via ldsm4 (2 n8-tiles/load), all 8 accumulators covered per
// k-step -> HMMA dep distance 8. C tiles: cp.async 2-slot ring.
// =================================================================================
#define ROWB    272                 // padded bf16 row: 136 halves
#define QSPLIT  (128 * ROWB)        // 34816
#define QBYTES  (3 * QSPLIT)        // 104448
#define CSPLIT  (64 * ROWB)         // 17408
#define CBUF    (3 * CSPLIT)        // 52224
#define RING_OFF QBYTES
#define SQN_OFF (QBYTES + 2 * CBUF) // 208896
#define KNN_SMEM (SQN_OFF + 2 * 256) // 209408

__device__ __forceinline__ void loadQ(uint32_t smdst,
                                      const __nv_bfloat16* __restrict__ Hh,
                                      const __nv_bfloat16* __restrict__ Hm,
                                      const __nv_bfloat16* __restrict__ Hl,
                                      int rowBase, int t)
{
#pragma unroll
    for (int i = 0; i < 24; i++) {
        int lin = t + i * 256;            // [0,6144)
        int s = lin >> 11, rem = lin & 2047;
        int row = rem >> 4, ch = rem & 15;
        const __nv_bfloat16* sp = (s == 0) ? Hh : (s == 1) ? Hm : Hl;
        cp16(smdst + (uint32_t)(s * QSPLIT + row * ROWB + ch * 16),
             (const char*)(sp + (size_t)(rowBase + row) * 128) + ch * 16);
    }
}

__device__ __forceinline__ void loadC(uint32_t smdst,
                                      const __nv_bfloat16* __restrict__ Hh,
                                      const __nv_bfloat16* __restrict__ Hm,
                                      const __nv_bfloat16* __restrict__ Hl,
                                      int rowBase, int t)
{
#pragma unroll
    for (int i = 0; i < 12; i++) {
        int lin = t + i * 256;            // [0,3072)
        int s = lin >> 10, rem = lin & 1023;
        int row = rem >> 4, ch = rem & 15;
        const __nv_bfloat16* sp = (s == 0) ? Hh : (s == 1) ? Hm : Hl;
        cp16(smdst + (uint32_t)(s * CSPLIT + row * ROWB + ch * 16),
             (const char*)(sp + (size_t)(rowBase + row) * 128) + ch * 16);
    }
}

// register insertion into sorted top-9 (strict <, stable for ascending-j feed)
#define INS9(Bst, Idx, KEY, J) do {                                        \
    float _k = (KEY); int _j = (J);                                        \
    if (_k < Bst[8]) {                                                     \
        float ck = _k; int cj = _j;                                        \
        _Pragma("unroll")                                                  \
        for (int _p = 0; _p < 9; _p++) {                                   \
            if (ck < Bst[_p]) {                                            \
                float tk = Bst[_p]; int tj = Idx[_p];                      \
                Bst[_p] = ck; Idx[_p] = cj; ck = tk; cj = tj;              \
            }                                                              \
        }                                                                  \
    }                                                                      \
} while (0)

__global__ __launch_bounds__(256, 1) void knn_mma(const __nv_bfloat16* __restrict__ Hh,
                                                  const __nv_bfloat16* __restrict__ Hm,
                                                  const __nv_bfloat16* __restrict__ Hl,
                                                  const float* __restrict__ h,
                                                  const float* __restrict__ sq,
                                                  float* __restrict__ agg)
{
    extern __shared__ __align__(16) char smp[];
    const uint32_t smb = smem_u32(smp);
    const int t = threadIdx.x, w = t >> 5, lane = t & 31;
    const int b = blockIdx.y, bOff = b * NPTS, r0 = blockIdx.x * 128;

    // prologue: Q resident load + prime 2-slot ring with tiles 0,1
    loadQ(smb, Hh, Hm, Hl, bOff + r0, t);
    CP_COMMIT();
#pragma unroll
    for (int pt = 0; pt < 2; pt++) {
        loadC(smb + (uint32_t)(RING_OFF + pt * CBUF), Hh, Hm, Hl, bOff + pt * 64, t);
        if (t < 16) cp16(smb + (uint32_t)(SQN_OFF + pt * 256 + t * 16),
                         (const char*)(sq + bOff + pt * 64) + t * 16);
        CP_COMMIT();
    }

    // per-lane top-9 for two accumulator rows
    float bA[9], bB[9];
    int   iA[9], iB[9];
#pragma unroll
    for (int p = 0; p < 9; p++) { bA[p] = 3.0e38f; bB[p] = 3.0e38f; iA[p] = 0; iB[p] = 0; }

    // ldmatrix lane addressing
    const uint32_t aoff = (uint32_t)((w * 16 + (lane & 15)) * ROWB + ((lane >> 4) * 16));
    const uint32_t boff = (uint32_t)(((lane & 7) + ((lane & 16) ? 8 : 0)) * ROWB
                                     + ((lane & 8) ? 16 : 0));
    const int cq = 2 * (lane & 3);
    const int sa[6] = {0, 0, 1, 0, 2, 1};
    const int sb[6] = {0, 1, 0, 2, 0, 1};

    for (int ct = 0; ct < 64; ct++) {
        if (ct < 63) CP_WAIT(1); else CP_WAIT(0);
        __syncthreads();

        const uint32_t cb = smb + (uint32_t)(RING_OFF + (ct & 1) * CBUF);

        float acc[8][4];
#pragma unroll
        for (int n8 = 0; n8 < 8; n8++)
#pragma unroll
            for (int q = 0; q < 4; q++) acc[n8][q] = 0.f;

#pragma unroll
        for (int ks = 0; ks < 8; ks++) {
            uint32_t Af[3][4];
#pragma unroll
            for (int s = 0; s < 3; s++)
                ldsm4(Af[s], smb + (uint32_t)(s * QSPLIT + ks * 32) + aoff);
            uint32_t Bf[4][3][4];
#pragma unroll
            for (int np = 0; np < 4; np++)
#pragma unroll
                for (int s = 0; s < 3; s++)
                    ldsm4(Bf[np][s], cb + (uint32_t)(s * CSPLIT + np * 16 * ROWB + ks * 32) + boff);
#pragma unroll
            for (int p = 0; p < 6; p++)
#pragma unroll
                for (int np = 0; np < 4; np++) {
                    mma16816(acc[np * 2 + 0], Af[sa[p]], Bf[np][sb[p]][0], Bf[np][sb[p]][1]);
                    mma16816(acc[np * 2 + 1], Af[sa[p]], Bf[np][sb[p]][2], Bf[np][sb[p]][3]);
                }
        }

        // in-register selection: key = sq[j] - 2*dot, ascending j within lane
        const float* sqt = (const float*)(smp + SQN_OFF + (ct & 1) * 256);
        const int jg0 = ct * 64;
#pragma unroll
        for (int n8 = 0; n8 < 8; n8++) {
            float s0 = sqt[n8 * 8 + cq];
            float s1 = sqt[n8 * 8 + cq + 1];
            int c0 = jg0 + n8 * 8 + cq;
            INS9(bA, iA, fmaf(-2.f, acc[n8][0], s0), c0);
            INS9(bA, iA, fmaf(-2.f, acc[n8][1], s1), c0 + 1);
            INS9(bB, iB, fmaf(-2.f, acc[n8][2], s0), c0);
            INS9(bB, iB, fmaf(-2.f, acc[n8][3], s1), c0 + 1);
        }

        __syncthreads();   // all warps done reading slot ct&1 before refilling it
        if (ct + 2 < 64) {
            loadC(smb + (uint32_t)(RING_OFF + (ct & 1) * CBUF), Hh, Hm, Hl,
                  bOff + (ct + 2) * 64, t);
            if (t < 16) cp16(smb + (uint32_t)(SQN_OFF + (ct & 1) * 256 + t * 16),
                             (const char*)(sq + bOff + (ct + 2) * 64) + t * 16);
            CP_COMMIT();
        }
    }

    // ---- merge per-lane candidates: 4 lanes x 9 -> top-9 per row ----
    __syncthreads();
    float* ckey = (float*)smp;                       // [128][36]
    int*   cidx = (int*)(smp + 128 * 36 * 4);        // [128][36]
    int*   nbx  = (int*)(smp + 2 * 128 * 36 * 4);    // [128][9]
    {
        const int rA = w * 16 + (lane >> 2);
        const int rB = rA + 8;
        const int sl = (lane & 3) * 9;
#pragma unroll
        for (int p = 0; p < 9; p++) {
            ckey[rA * 36 + sl + p] = bA[p];  cidx[rA * 36 + sl + p] = iA[p];
            ckey[rB * 36 + sl + p] = bB[p];  cidx[rB * 36 + sl + p] = iB[p];
        }
    }
    __syncthreads();

    if (t < 128) {
        float bk[9]; int bj[9];
#pragma unroll
        for (int p = 0; p < 9; p++) { bk[p] = 3.0e38f; bj[p] = 0x7fffffff; }
        for (int q = 0; q < 36; q++) {
            float k = ckey[t * 36 + q];
            int   j = cidx[t * 36 + q];
            if (k < bk[8] || (k == bk[8] && j < bj[8])) {
                float ck = k; int cj = j;
#pragma unroll
                for (int p = 0; p < 9; p++) {
                    if (ck < bk[p] || (ck == bk[p] && cj < bj[p])) {
                        float tk = bk[p]; int tj = bj[p];
                        bk[p] = ck; bj[p] = cj; ck = tk; cj = tj;
                    }
                }
            }
        }
#pragma unroll
        for (int p = 0; p < 9; p++) nbx[t * 9 + p] = bj[p];
    }
    __syncthreads();

    // ---- cooperative gather + max-relative aggregation (warp per 16 rows) ----
    for (int rr = 0; rr < 16; rr++) {
        const int row = w * 16 + rr;
        float4 q = *(const float4*)&h[(size_t)(bOff + r0 + row) * 128 + lane * 4];
        float m0 = -3.0e38f, m1 = -3.0e38f, m2 = -3.0e38f, m3 = -3.0e38f;
#pragma unroll
        for (int p = 0; p < KTOP; p++) {
            int j = nbx[row * 9 + p];
            float4 v = *(const float4*)&h[(size_t)(bOff + j) * 128 + lane * 4];
            m0 = fmaxf(m0, v.x); m1 = fmaxf(m1, v.y);
            m2 = fmaxf(m2, v.z); m3 = fmaxf(m3, v.w);
        }
        *(float4*)&agg[(size_t)(bOff + r0 + row) * 128 + lane * 4] =
            make_float4(m0 - q.x, m1 - q.y, m2 - q.z, m3 - q.w);
    }
}

// =================================================================================
// Launch sequence
// =================================================================================
extern "C" void kernel_launch(void* const* d_in, const int* in_sizes, int n_in,
                              void* d_out, int out_size)
{
    const float* x   = (const float*)d_in[0];
    const float* W1  = (const float*)d_in[1];
    const float* b1  = (const float*)d_in[2];
    const float* g1  = (const float*)d_in[3];
    const float* be1 = (const float*)d_in[4];
    const float* Wg  = (const float*)d_in[5];
    const float* bg  = (const float*)d_in[6];
    const float* gg  = (const float*)d_in[7];
    const float* beg = (const float*)d_in[8];
    const float* W2  = (const float*)d_in[9];
    const float* b2  = (const float*)d_in[10];
    const float* g2  = (const float*)d_in[11];
    const float* be2 = (const float*)d_in[12];
    float* out = (float*)d_out;

    float *ph, *pagg, *pt2, *psq;
    __nv_bfloat16 *phh, *phm, *phl;
    cudaGetSymbolAddress((void**)&ph,   g_h);
    cudaGetSymbolAddress((void**)&pagg, g_agg);
    cudaGetSymbolAddress((void**)&pt2,  g_t2);
    cudaGetSymbolAddress((void**)&psq,  g_sq);
    cudaGetSymbolAddress((void**)&phh,  g_hh);
    cudaGetSymbolAddress((void**)&phm,  g_hm);
    cudaGetSymbolAddress((void**)&phl,  g_hl);

    cudaFuncSetAttribute(knn_mma, cudaFuncAttributeMaxDynamicSharedMemorySize, KNN_SMEM);

    // fc1 (+fused stats) + BN/split/norms
    gemm128<<<256, 256>>>(x, nullptr, W1, b1, ph);
    colstat_final<<<1, 128>>>();
    bn_split<<<4096, 256>>>(ph, g1, be1, ph, phh, phm, phl, psq);

    // KNN + max-relative aggregation (tensor cores via mma.sync)
    knn_mma<<<dim3(32, 8), 256, KNN_SMEM>>>(phh, phm, phl, ph, psq, pagg);

    // graph conv MLP: cat([h, agg]) @ Wg + bg (single fused 256-K GEMM), BN, GELU
    gemm128<<<256, 256>>>(ph, pagg, Wg, bg, pt2);
    colstat_final<<<1, 128>>>();
    bn_apply<<<4096, 256>>>(pt2, gg, beg, nullptr, pt2, 1);

    // fc2 (+fused stats) + BN + residual
    gemm128<<<256, 256>>>(pt2, nullptr, W2, b2, out);
    colstat_final<<<1, 128>>>();
    bn_apply<<<4096, 256>>>(out, g2, be2, x, out, 2);
}

// round 9
// speedup vs baseline: 3.1279x; 1.3130x over previous
#include <cuda_runtime.h>
#include <cuda_fp16.h>
#include <cuda_bf16.h>
#include <math.h>
#include <stdint.h>

// Problem constants
#define BSZ   8
#define NPTS  4096
#define CDIM  128
#define KTOP  9
#define MROWS (BSZ * NPTS)   // 32768
#define EPSBN 1e-5f

// ---------------- scratch (device globals; no allocation allowed) ----------------
__device__ float g_h  [MROWS * CDIM];
__device__ float g_agg[MROWS * CDIM];
__device__ float g_t2 [MROWS * CDIM];
__device__ float g_sq [MROWS];
__device__ __half g_hh[MROWS * CDIM];   // fp16 hi split of h
__device__ __half g_hm[MROWS * CDIM];   // fp16 mid split (residual)
__device__ float g_psum[256 * 128];
__device__ float g_psq [256 * 128];
__device__ float g_mean[128];
__device__ float g_rstd[128];

// =================================================================================
// PTX helpers (baseline sm_80+ ISA only: ldmatrix / mma.sync / cp.async)
// =================================================================================
__device__ __forceinline__ uint32_t smem_u32(const void* p) {
    uint32_t a;
    asm("{ .reg .u64 t; cvta.to.shared.u64 t, %1; cvt.u32.u64 %0, t; }" : "=r"(a) : "l"(p));
    return a;
}
__device__ __forceinline__ void ldsm4(uint32_t* r, uint32_t a) {
    asm volatile("ldmatrix.sync.aligned.m8n8.x4.shared.b16 {%0,%1,%2,%3}, [%4];"
                 : "=r"(r[0]), "=r"(r[1]), "=r"(r[2]), "=r"(r[3]) : "r"(a));
}
__device__ __forceinline__ void mma16816h(float* c, const uint32_t* a, uint32_t b0, uint32_t b1) {
    asm volatile("mma.sync.aligned.m16n8k16.row.col.f32.f16.f16.f32 "
                 "{%0,%1,%2,%3},{%4,%5,%6,%7},{%8,%9},{%0,%1,%2,%3};"
                 : "+f"(c[0]), "+f"(c[1]), "+f"(c[2]), "+f"(c[3])
                 : "r"(a[0]), "r"(a[1]), "r"(a[2]), "r"(a[3]), "r"(b0), "r"(b1));
}
__device__ __forceinline__ void cp16(uint32_t dst, const void* src) {
    asm volatile("cp.async.cg.shared.global [%0], [%1], 16;" :: "r"(dst), "l"(src));
}
#define CP_COMMIT() asm volatile("cp.async.commit_group;" ::: "memory")
#define CP_WAIT(n)  asm volatile("cp.async.wait_group %0;" :: "n"(n) : "memory")

// =================================================================================
// Tiled SGEMM: out[M x 128] = A[M x 128] @ W (+ A2 @ W[128:]) + bias.
// Fused deterministic column stats (sum / sumsq) into the epilogue.
// =================================================================================
__global__ __launch_bounds__(256) void gemm128(const float* __restrict__ A,
                                               const float* __restrict__ A2,
                                               const float* __restrict__ W,
                                               const float* __restrict__ bias,
                                               float* __restrict__ out)
{
    __shared__ float As[32 * 132];
    __shared__ float Ws[32 * 132];
    const int t  = threadIdx.x;
    const int tx = t & 15, ty = t >> 4;
    const int r0 = blockIdx.x * 128;

    float c[8][8];
#pragma unroll
    for (int i = 0; i < 8; i++)
#pragma unroll
        for (int j = 0; j < 8; j++) c[i][j] = 0.f;

    const int nSrc = A2 ? 2 : 1;
    for (int si = 0; si < nSrc; si++) {
        const float* Ap = si ? A2 : A;
        const float* Wp = W + si * 128 * 128;
        for (int kc = 0; kc < 128; kc += 32) {
            __syncthreads();
#pragma unroll
            for (int i = 0; i < 4; i++) {
                int lin = t + i * 256;
                int m = lin >> 3, kq = lin & 7;
                float4 v = *(const float4*)&Ap[(size_t)(r0 + m) * 128 + kc + kq * 4];
                As[(kq * 4 + 0) * 132 + m] = v.x;
                As[(kq * 4 + 1) * 132 + m] = v.y;
                As[(kq * 4 + 2) * 132 + m] = v.z;
                As[(kq * 4 + 3) * 132 + m] = v.w;
            }
#pragma unroll
            for (int i = 0; i < 4; i++) {
                int lin = t + i * 256;
                int k = lin >> 5, n4 = lin & 31;
                float4 v = *(const float4*)&Wp[(size_t)(kc + k) * 128 + n4 * 4];
                *(float4*)&Ws[k * 132 + n4 * 4] = v;
            }
            __syncthreads();
#pragma unroll 8
            for (int k = 0; k < 32; k++) {
                float4 a0 = *(const float4*)&As[k * 132 + ty * 8];
                float4 a1 = *(const float4*)&As[k * 132 + ty * 8 + 4];
                float4 b0 = *(const float4*)&Ws[k * 132 + tx * 8];
                float4 b1 = *(const float4*)&Ws[k * 132 + tx * 8 + 4];
                float a[8] = {a0.x, a0.y, a0.z, a0.w, a1.x, a1.y, a1.z, a1.w};
                float b[8] = {b0.x, b0.y, b0.z, b0.w, b1.x, b1.y, b1.z, b1.w};
#pragma unroll
                for (int i = 0; i < 8; i++)
#pragma unroll
                    for (int j = 0; j < 8; j++) c[i][j] = fmaf(a[i], b[j], c[i][j]);
            }
        }
    }

    float bv[8];
#pragma unroll
    for (int j = 0; j < 8; j++) bv[j] = bias ? bias[tx * 8 + j] : 0.f;

    float s1[8], s2[8];
#pragma unroll
    for (int j = 0; j < 8; j++) { s1[j] = 0.f; s2[j] = 0.f; }

#pragma unroll
    for (int i = 0; i < 8; i++) {
        size_t base = (size_t)(r0 + ty * 8 + i) * 128 + tx * 8;
        float v[8];
#pragma unroll
        for (int j = 0; j < 8; j++) {
            v[j] = c[i][j] + bv[j];
            s1[j] += v[j];
            s2[j] += v[j] * v[j];
        }
        *(float4*)&out[base]     = make_float4(v[0], v[1], v[2], v[3]);
        *(float4*)&out[base + 4] = make_float4(v[4], v[5], v[6], v[7]);
    }

    __syncthreads();
#pragma unroll
    for (int j = 0; j < 8; j++) {
        As[ty * 128 + tx * 8 + j] = s1[j];
        Ws[ty * 128 + tx * 8 + j] = s2[j];
    }
    __syncthreads();
    if (t < 128) {
        float S = 0.f, Q = 0.f;
#pragma unroll
        for (int g = 0; g < 16; g++) { S += As[g * 128 + t]; Q += Ws[g * 128 + t]; }
        g_psum[blockIdx.x * 128 + t] = S;
        g_psq [blockIdx.x * 128 + t] = Q;
    }
}

__global__ void colstat_final()
{
    const int t = threadIdx.x;
    float s = 0.f, s2 = 0.f;
    for (int b = 0; b < 256; b++) { s += g_psum[b * 128 + t]; s2 += g_psq[b * 128 + t]; }
    float m   = s / (float)MROWS;
    float var = s2 / (float)MROWS - m * m;
    g_mean[t] = m;
    g_rstd[t] = rsqrtf(var + EPSBN);
}

// ============ BN apply (mode 1: +GELU, mode 2: +residual) ============
__global__ void bn_apply(const float* __restrict__ X, const float* __restrict__ gamma,
                         const float* __restrict__ beta, const float* __restrict__ resid,
                         float* __restrict__ Y, int mode)
{
    const int i4 = blockIdx.x * blockDim.x + threadIdx.x;
    const size_t i = (size_t)i4 * 4;
    const int ch = (int)(i & 127);
    float4 v  = *(const float4*)&X[i];
    float4 ga = *(const float4*)&gamma[ch];
    float4 be = *(const float4*)&beta[ch];
    float4 mn = *(const float4*)&g_mean[ch];
    float4 rs = *(const float4*)&g_rstd[ch];
    float o[4];
    o[0] = ga.x * (v.x - mn.x) * rs.x + be.x;
    o[1] = ga.y * (v.y - mn.y) * rs.y + be.y;
    o[2] = ga.z * (v.z - mn.z) * rs.z + be.z;
    o[3] = ga.w * (v.w - mn.w) * rs.w + be.w;
    if (mode == 1) {
#pragma unroll
        for (int j = 0; j < 4; j++)
            o[j] = 0.5f * o[j] * (1.f + erff(o[j] * 0.70710678118654752f));
    } else if (mode == 2) {
        float4 r = *(const float4*)&resid[i];
        o[0] += r.x; o[1] += r.y; o[2] += r.z; o[3] += r.w;
    }
    *(float4*)&Y[i] = make_float4(o[0], o[1], o[2], o[3]);
}

// ===== BN apply + fp16 2-way split + row sq-norm (fc1 output), warp per row =====
__global__ void bn_split(const float* __restrict__ X, const float* __restrict__ gamma,
                         const float* __restrict__ beta, float* __restrict__ H,
                         __half* __restrict__ Hh, __half* __restrict__ Hm,
                         float* __restrict__ sqo)
{
    const int wid = threadIdx.x >> 5, lane = threadIdx.x & 31;
    const int row = blockIdx.x * 8 + wid;
    const int ch = lane * 4;
    const size_t base = (size_t)row * 128 + ch;
    float4 v  = *(const float4*)&X[base];
    float4 ga = *(const float4*)&gamma[ch];
    float4 be = *(const float4*)&beta[ch];
    float4 mn = *(const float4*)&g_mean[ch];
    float4 rs = *(const float4*)&g_rstd[ch];
    float o[4];
    o[0] = ga.x * (v.x - mn.x) * rs.x + be.x;
    o[1] = ga.y * (v.y - mn.y) * rs.y + be.y;
    o[2] = ga.z * (v.z - mn.z) * rs.z + be.z;
    o[3] = ga.w * (v.w - mn.w) * rs.w + be.w;
    *(float4*)&H[base] = make_float4(o[0], o[1], o[2], o[3]);

    __half hh[4], hm[4];
#pragma unroll
    for (int j = 0; j < 4; j++) {
        hh[j] = __float2half_rn(o[j]);
        hm[j] = __float2half_rn(o[j] - __half2float(hh[j]));
    }
    ((__half2*)(Hh + base))[0] = __halves2half2(hh[0], hh[1]);
    ((__half2*)(Hh + base))[1] = __halves2half2(hh[2], hh[3]);
    ((__half2*)(Hm + base))[0] = __halves2half2(hm[0], hm[1]);
    ((__half2*)(Hm + base))[1] = __halves2half2(hm[2], hm[3]);

    float s = o[0]*o[0] + o[1]*o[1] + o[2]*o[2] + o[3]*o[3];
#pragma unroll
    for (int off = 16; off; off >>= 1) s += __shfl_xor_sync(0xffffffffu, s, off);
    if (lane == 0) sqo[row] = s;
}

// =================================================================================
// KNN + max-relative aggregation via mma.sync fp16 2-split (3 products).
// 512 threads (16 warps). Q tile (128 rows x 2 splits) resident in SMEM.
// Warps: (w&7) selects 16-row strip, (w>>3) selects 32-col half of the 64-col tile.
// C tiles: cp.async 3-slot ring, 2-tile prefetch distance, ONE barrier per tile.
// =================================================================================
#define ROWB    272                 // padded fp16 row: 136 halves
#define QSPLIT  (128 * ROWB)        // 34816
#define QBYTES  (2 * QSPLIT)        // 69632
#define CSPLIT  (64 * ROWB)         // 17408
#define CBUF    (2 * CSPLIT)        // 34816
#define RING_OFF QBYTES
#define SQN_OFF (RING_OFF + 3 * CBUF)  // 174080
#define KNN_SMEM (SQN_OFF + 3 * 256)   // 174848

__device__ __forceinline__ void loadQ(uint32_t smdst,
                                      const __half* __restrict__ Hh,
                                      const __half* __restrict__ Hm,
                                      int rowBase, int t)
{
#pragma unroll
    for (int i = 0; i < 8; i++) {
        int lin = t + i * 512;            // [0,4096)
        int s = lin >> 11, rem = lin & 2047;
        int row = rem >> 4, ch = rem & 15;
        const __half* sp = s ? Hm : Hh;
        cp16(smdst + (uint32_t)(s * QSPLIT + row * ROWB + ch * 16),
             (const char*)(sp + (size_t)(rowBase + row) * 128) + ch * 16);
    }
}

__device__ __forceinline__ void loadC(uint32_t smdst,
                                      const __half* __restrict__ Hh,
                                      const __half* __restrict__ Hm,
                                      int rowBase, int t)
{
#pragma unroll
    for (int i = 0; i < 4; i++) {
        int lin = t + i * 512;            // [0,2048)
        int s = lin >> 10, rem = lin & 1023;
        int row = rem >> 4, ch = rem & 15;
        const __half* sp = s ? Hm : Hh;
        cp16(smdst + (uint32_t)(s * CSPLIT + row * ROWB + ch * 16),
             (const char*)(sp + (size_t)(rowBase + row) * 128) + ch * 16);
    }
}

// register insertion into sorted top-9 (strict <, stable for ascending-j feed)
#define INS9(Bst, Idx, KEY, J) do {                                        \
    float _k = (KEY); int _j = (J);                                        \
    if (_k < Bst[8]) {                                                     \
        float ck = _k; int cj = _j;                                        \
        _Pragma("unroll")                                                  \
        for (int _p = 0; _p < 9; _p++) {                                   \
            if (ck < Bst[_p]) {                                            \
                float tk = Bst[_p]; int tj = Idx[_p];                      \
                Bst[_p] = ck; Idx[_p] = cj; ck = tk; cj = tj;              \
            }                                                              \
        }                                                                  \
    }                                                                      \
} while (0)

__global__ __launch_bounds__(512, 1) void knn_mma(const __half* __restrict__ Hh,
                                                  const __half* __restrict__ Hm,
                                                  const float* __restrict__ h,
                                                  const float* __restrict__ sq,
                                                  float* __restrict__ agg)
{
    extern __shared__ __align__(16) char smp[];
    const uint32_t smb = smem_u32(smp);
    const int t = threadIdx.x, w = t >> 5, lane = t & 31;
    const int wr = w & 7;          // 16-row strip
    const int wc = w >> 3;         // 32-col half
    const int b = blockIdx.y, bOff = b * NPTS, r0 = blockIdx.x * 128;

    // prologue: Q resident + prime ring with tiles 0,1
    loadQ(smb, Hh, Hm, bOff + r0, t);
    CP_COMMIT();
#pragma unroll
    for (int pt = 0; pt < 2; pt++) {
        loadC(smb + (uint32_t)(RING_OFF + pt * CBUF), Hh, Hm, bOff + pt * 64, t);
        if (t < 16) cp16(smb + (uint32_t)(SQN_OFF + pt * 256 + t * 16),
                         (const char*)(sq + bOff + pt * 64) + t * 16);
        CP_COMMIT();
    }

    // per-lane top-9 for two accumulator rows
    float bA[9], bB[9];
    int   iA[9], iB[9];
#pragma unroll
    for (int p = 0; p < 9; p++) { bA[p] = 3.0e38f; bB[p] = 3.0e38f; iA[p] = 0; iB[p] = 0; }

    const uint32_t aoff = (uint32_t)((wr * 16 + (lane & 15)) * ROWB + ((lane >> 4) * 16));
    const uint32_t boff = (uint32_t)(((lane & 7) + ((lane & 16) ? 8 : 0)) * ROWB
                                     + ((lane & 8) ? 16 : 0));
    const int cq = 2 * (lane & 3);
    const int sa[3] = {0, 0, 1};
    const int sb[3] = {0, 1, 0};

    for (int ct = 0; ct < 64; ct++) {
        if (ct < 63) CP_WAIT(1); else CP_WAIT(0);
        __syncthreads();   // tile ct ready AND all warps done with tile ct-1

        if (ct + 2 < 64) {
            loadC(smb + (uint32_t)(RING_OFF + ((ct + 2) % 3) * CBUF), Hh, Hm,
                  bOff + (ct + 2) * 64, t);
            if (t < 16) cp16(smb + (uint32_t)(SQN_OFF + ((ct + 2) % 3) * 256 + t * 16),
                             (const char*)(sq + bOff + (ct + 2) * 64) + t * 16);
            CP_COMMIT();
        }

        const uint32_t cb = smb + (uint32_t)(RING_OFF + (ct % 3) * CBUF)
                          + (uint32_t)(wc * 32 * ROWB);

        float acc[4][4];
#pragma unroll
        for (int n8 = 0; n8 < 4; n8++)
#pragma unroll
            for (int q = 0; q < 4; q++) acc[n8][q] = 0.f;

#pragma unroll
        for (int ks = 0; ks < 8; ks++) {
            uint32_t Af[2][4];
#pragma unroll
            for (int s = 0; s < 2; s++)
                ldsm4(Af[s], smb + (uint32_t)(s * QSPLIT + ks * 32) + aoff);
            uint32_t Bf[2][2][4];
#pragma unroll
            for (int np = 0; np < 2; np++)
#pragma unroll
                for (int s = 0; s < 2; s++)
                    ldsm4(Bf[np][s], cb + (uint32_t)(s * CSPLIT + np * 16 * ROWB + ks * 32) + boff);
#pragma unroll
            for (int p = 0; p < 3; p++)
#pragma unroll
                for (int np = 0; np < 2; np++) {
                    mma16816h(acc[np * 2 + 0], Af[sa[p]], Bf[np][sb[p]][0], Bf[np][sb[p]][1]);
                    mma16816h(acc[np * 2 + 1], Af[sa[p]], Bf[np][sb[p]][2], Bf[np][sb[p]][3]);
                }
        }

        // in-register selection: key = sq[j] - 2*dot, ascending j within lane
        const float* sqt = (const float*)(smp + SQN_OFF + (ct % 3) * 256) + wc * 32;
        const int jg0 = ct * 64 + wc * 32;
#pragma unroll
        for (int n8 = 0; n8 < 4; n8++) {
            float s0 = sqt[n8 * 8 + cq];
            float s1 = sqt[n8 * 8 + cq + 1];
            int c0 = jg0 + n8 * 8 + cq;
            INS9(bA, iA, fmaf(-2.f, acc[n8][0], s0), c0);
            INS9(bA, iA, fmaf(-2.f, acc[n8][1], s1), c0 + 1);
            INS9(bB, iB, fmaf(-2.f, acc[n8][2], s0), c0);
            INS9(bB, iB, fmaf(-2.f, acc[n8][3], s1), c0 + 1);
        }
    }

    // ---- merge per-row candidates: 8 contributor lanes x 9 -> top-9 per row ----
    __syncthreads();
    float* ckey = (float*)smp;                       // [128][72]
    int*   cidx = (int*)(smp + 128 * 72 * 4);        // [128][72]
    int*   nbx  = (int*)(smp + 2 * 128 * 72 * 4);    // [128][9]
    {
        const int rA = wr * 16 + (lane >> 2);
        const int rB = rA + 8;
        const int sl = (wc * 4 + (lane & 3)) * 9;
#pragma unroll
        for (int p = 0; p < 9; p++) {
            ckey[rA * 72 + sl + p] = bA[p];  cidx[rA * 72 + sl + p] = iA[p];
            ckey[rB * 72 + sl + p] = bB[p];  cidx[rB * 72 + sl + p] = iB[p];
        }
    }
    __syncthreads();

    if (t < 128) {
        float bk[9]; int bj[9];
#pragma unroll
        for (int p = 0; p < 9; p++) { bk[p] = 3.0e38f; bj[p] = 0x7fffffff; }
        for (int q = 0; q < 72; q++) {
            float k = ckey[t * 72 + q];
            int   j = cidx[t * 72 + q];
            if (k < bk[8] || (k == bk[8] && j < bj[8])) {
                float ck = k; int cj = j;
#pragma unroll
                for (int p = 0; p < 9; p++) {
                    if (ck < bk[p] || (ck == bk[p] && cj < bj[p])) {
                        float tk = bk[p]; int tj = bj[p];
                        bk[p] = ck; bj[p] = cj; ck = tk; cj = tj;
                    }
                }
            }
        }
#pragma unroll
        for (int p = 0; p < 9; p++) nbx[t * 9 + p] = bj[p];
    }
    __syncthreads();

    // ---- cooperative gather + max-relative aggregation (warp per 8 rows) ----
    for (int rr = 0; rr < 8; rr++) {
        const int row = w * 8 + rr;
        float4 q = *(const float4*)&h[(size_t)(bOff + r0 + row) * 128 + lane * 4];
        float m0 = -3.0e38f, m1 = -3.0e38f, m2 = -3.0e38f, m3 = -3.0e38f;
#pragma unroll
        for (int p = 0; p < KTOP; p++) {
            int j = nbx[row * 9 + p];
            float4 v = *(const float4*)&h[(size_t)(bOff + j) * 128 + lane * 4];
            m0 = fmaxf(m0, v.x); m1 = fmaxf(m1, v.y);
            m2 = fmaxf(m2, v.z); m3 = fmaxf(m3, v.w);
        }
        *(float4*)&agg[(size_t)(bOff + r0 + row) * 128 + lane * 4] =
            make_float4(m0 - q.x, m1 - q.y, m2 - q.z, m3 - q.w);
    }
}

// =================================================================================
// Launch sequence
// =================================================================================
extern "C" void kernel_launch(void* const* d_in, const int* in_sizes, int n_in,
                              void* d_out, int out_size)
{
    const float* x   = (const float*)d_in[0];
    const float* W1  = (const float*)d_in[1];
    const float* b1  = (const float*)d_in[2];
    const float* g1  = (const float*)d_in[3];
    const float* be1 = (const float*)d_in[4];
    const float* Wg  = (const float*)d_in[5];
    const float* bg  = (const float*)d_in[6];
    const float* gg  = (const float*)d_in[7];
    const float* beg = (const float*)d_in[8];
    const float* W2  = (const float*)d_in[9];
    const float* b2  = (const float*)d_in[10];
    const float* g2  = (const float*)d_in[11];
    const float* be2 = (const float*)d_in[12];
    float* out = (float*)d_out;

    float *ph, *pagg, *pt2, *psq;
    __half *phh, *phm;
    cudaGetSymbolAddress((void**)&ph,   g_h);
    cudaGetSymbolAddress((void**)&pagg, g_agg);
    cudaGetSymbolAddress((void**)&pt2,  g_t2);
    cudaGetSymbolAddress((void**)&psq,  g_sq);
    cudaGetSymbolAddress((void**)&phh,  g_hh);
    cudaGetSymbolAddress((void**)&phm,  g_hm);

    cudaFuncSetAttribute(knn_mma, cudaFuncAttributeMaxDynamicSharedMemorySize, KNN_SMEM);

    // fc1 (+fused stats) + BN/split/norms
    gemm128<<<256, 256>>>(x, nullptr, W1, b1, ph);
    colstat_final<<<1, 128>>>();
    bn_split<<<4096, 256>>>(ph, g1, be1, ph, phh, phm, psq);

    // KNN + max-relative aggregation (tensor cores via mma.sync, fp16 2-split)
    knn_mma<<<dim3(32, 8), 512, KNN_SMEM>>>(phh, phm, ph, psq, pagg);

    // graph conv MLP: cat([h, agg]) @ Wg + bg (single fused 256-K GEMM), BN, GELU
    gemm128<<<256, 256>>>(ph, pagg, Wg, bg, pt2);
    colstat_final<<<1, 128>>>();
    bn_apply<<<4096, 256>>>(pt2, gg, beg, nullptr, pt2, 1);

    // fc2 (+fused stats) + BN + residual
    gemm128<<<256, 256>>>(pt2, nullptr, W2, b2, out);
    colstat_final<<<1, 128>>>();
    bn_apply<<<4096, 256>>>(out, g2, be2, x, out, 2);
}